// round 10
// baseline (speedup 1.0000x reference)
#include <cuda_runtime.h>
#include <cstdint>

#define SIGMA_INV 10000.0f  // 1 / 1e-4

// factor = 1 - prob = 1 - sigmoid(-d/sigma)*mask = mask ? sigmoid(d/sigma) : 1
__device__ __forceinline__ float blend_factor(float d, int face) {
    float s = __fdividef(1.0f, 1.0f + __expf(-d * SIGMA_INV));
    return (face >= 0) ? s : 1.0f;
}

// Persistent grid-stride version of the R5 scheme: 2 threads per pixel,
// front-batched 2x float4 + 2x int4 streaming loads, 1-shuffle reduce,
// one float4 store per pixel. Grid sized to exactly one wave.
__global__ void __launch_bounds__(256)
self_shader_kernel(const float* __restrict__ zbuf,
                   const float* __restrict__ dists,
                   const int* __restrict__ pix_to_face,
                   float* __restrict__ out,
                   int n_pix) {
    int sub = threadIdx.x & 1;            // which half of K=16
    int stride_pairs = (gridDim.x * blockDim.x) >> 1;   // pixel stride
    int pair0 = (blockIdx.x * blockDim.x + threadIdx.x) >> 1;

    const float4* d4b = reinterpret_cast<const float4*>(dists);
    const int4*   f4b = reinterpret_cast<const int4*>(pix_to_face);
    float4*       o4  = reinterpret_cast<float4*>(out);

    for (int pix = pair0; pix < n_pix; pix += stride_pairs) {
        size_t base = ((size_t)pix << 2) + (sub << 1);

        float4 d0 = __ldcs(d4b + base);
        float4 d1 = __ldcs(d4b + base + 1);
        int4   f0 = __ldcs(f4b + base);
        int4   f1 = __ldcs(f4b + base + 1);
        float  z  = __ldg(&zbuf[(size_t)pix << 4]);  // channel 0 only

        float prod = blend_factor(d0.x, f0.x) * blend_factor(d0.y, f0.y)
                   * blend_factor(d0.z, f0.z) * blend_factor(d0.w, f0.w);
        prod *= blend_factor(d1.x, f1.x) * blend_factor(d1.y, f1.y)
              * blend_factor(d1.z, f1.z) * blend_factor(d1.w, f1.w);

        // combine two halves (lanes 2p, 2p+1 adjacent in warp)
        prod *= __shfl_xor_sync(0xFFFFFFFFu, prod, 1);

        if (sub == 0) {
            __stcs(o4 + pix, make_float4(z, z, z, 1.0f - prod));
        }
    }
}

extern "C" void kernel_launch(void* const* d_in, const int* in_sizes, int n_in,
                              void* d_out, int out_size) {
    const float* zbuf  = (const float*)d_in[0];
    const float* dists = (const float*)d_in[1];
    const int*   p2f   = (const int*)d_in[2];
    float*       out   = (float*)d_out;

    int n_pix = in_sizes[0] / 16;   // N*H*W

    // Exactly one wave: 148 SMs (GB300: 152) x 8 blocks of 256 threads.
    // Use 152 to match GB300's SM count; extra blocks just round-robin.
    int block = 256;
    int grid  = 152 * 8;
    long long needed = ((long long)n_pix * 2 + block - 1) / block;
    if (needed < grid) grid = (int)needed;

    self_shader_kernel<<<grid, block>>>(zbuf, dists, p2f, out, n_pix);
}

// round 11
// speedup vs baseline: 1.0042x; 1.0042x over previous
#include <cuda_runtime.h>
#include <cstdint>

#define SIGMA_INV 10000.0f  // 1 / 1e-4

// factor = 1 - prob = 1 - sigmoid(-d/sigma)*mask = mask ? sigmoid(d/sigma) : 1
__device__ __forceinline__ float blend_factor(float d, int face) {
    float s = __fdividef(1.0f, 1.0f + __expf(-d * SIGMA_INV));
    return (face >= 0) ? s : 1.0f;
}

// Persistent grid-stride version of the R5 scheme: 2 threads per pixel,
// front-batched 2x float4 + 2x int4 streaming loads, 1-shuffle reduce,
// one float4 store per pixel. Grid sized to exactly one wave.
__global__ void __launch_bounds__(256)
self_shader_kernel(const float* __restrict__ zbuf,
                   const float* __restrict__ dists,
                   const int* __restrict__ pix_to_face,
                   float* __restrict__ out,
                   int n_pix) {
    int sub = threadIdx.x & 1;            // which half of K=16
    int stride_pairs = (gridDim.x * blockDim.x) >> 1;   // pixel stride
    int pair0 = (blockIdx.x * blockDim.x + threadIdx.x) >> 1;

    const float4* d4b = reinterpret_cast<const float4*>(dists);
    const int4*   f4b = reinterpret_cast<const int4*>(pix_to_face);
    float4*       o4  = reinterpret_cast<float4*>(out);

    for (int pix = pair0; pix < n_pix; pix += stride_pairs) {
        size_t base = ((size_t)pix << 2) + (sub << 1);

        float4 d0 = __ldcs(d4b + base);
        float4 d1 = __ldcs(d4b + base + 1);
        int4   f0 = __ldcs(f4b + base);
        int4   f1 = __ldcs(f4b + base + 1);
        float  z  = __ldg(&zbuf[(size_t)pix << 4]);  // channel 0 only

        float prod = blend_factor(d0.x, f0.x) * blend_factor(d0.y, f0.y)
                   * blend_factor(d0.z, f0.z) * blend_factor(d0.w, f0.w);
        prod *= blend_factor(d1.x, f1.x) * blend_factor(d1.y, f1.y)
              * blend_factor(d1.z, f1.z) * blend_factor(d1.w, f1.w);

        // combine two halves (lanes 2p, 2p+1 adjacent in warp)
        prod *= __shfl_xor_sync(0xFFFFFFFFu, prod, 1);

        if (sub == 0) {
            __stcs(o4 + pix, make_float4(z, z, z, 1.0f - prod));
        }
    }
}

extern "C" void kernel_launch(void* const* d_in, const int* in_sizes, int n_in,
                              void* d_out, int out_size) {
    const float* zbuf  = (const float*)d_in[0];
    const float* dists = (const float*)d_in[1];
    const int*   p2f   = (const int*)d_in[2];
    float*       out   = (float*)d_out;

    int n_pix = in_sizes[0] / 16;   // N*H*W

    // Exactly one wave: 148 SMs (GB300: 152) x 8 blocks of 256 threads.
    // Use 152 to match GB300's SM count; extra blocks just round-robin.
    int block = 256;
    int grid  = 152 * 8;
    long long needed = ((long long)n_pix * 2 + block - 1) / block;
    if (needed < grid) grid = (int)needed;

    self_shader_kernel<<<grid, block>>>(zbuf, dists, p2f, out, n_pix);
}